// round 8
// baseline (speedup 1.0000x reference)
#include <cuda_runtime.h>
#include <math.h>
#include <stdint.h>

// ContrastLoss: B=4, C=4096, K=1.
//
// lse_pairs_b   = log(sum_{lab=0} e^{pred}) + log(sum_{lab=1} e^{-pred})
// loss_contrast = (1/B) * sum_b logaddexp(lse_pairs_b, 0)
// loss_aux      = (1/B) * sum_b mean_c (aux - aux_label)^2
//
// R8: single sync stage. 8-CTA cluster x 256 threads, 8 elems/thread.
// Warp lane0s DSMEM-store partials straight into rank 0's smem (64 slots);
// one cluster barrier; rank 0 warp 0 reduces all slots in parallel.
// Deterministic: fixed slots, fixed butterfly order.

#define FULL 0xFFFFFFFFu
#define NBLK 8
#define NTHR 256
#define NSLOT (NBLK * (NTHR / 32))   // 64

__device__ __forceinline__ uint32_t smem_u32(const void* p) {
    uint32_t a;
    asm("{ .reg .u64 t; cvta.to.shared.u64 t, %1; cvt.u32.u64 %0, t; }"
        : "=r"(a) : "l"(p));
    return a;
}

__device__ __forceinline__ void acc_elem(float v, int lab, float& sn, float& sp) {
    float fl = (float)lab;
    float e  = __expf(v * fmaf(-2.f, fl, 1.f));  // exp(+v) if lab==0 else exp(-v)
    sn = fmaf(e, 1.f - fl, sn);
    sp = fmaf(e, fl, sp);
}

__global__ __launch_bounds__(NTHR, 1) __cluster_dims__(NBLK, 1, 1)
void contrast_loss_kernel(const float* __restrict__ contrast,
                          const int*   __restrict__ label,
                          const float* __restrict__ aux,
                          const float* __restrict__ aux_label,
                          float* __restrict__ out) {
    // Slot array: only rank 0's copy is used; identical layout in every CTA
    // so mapa translates local slot addresses to rank 0's.
    __shared__ float4 sclus[NSLOT];

    int tid = threadIdx.x;
    uint32_t rank;
    asm("mov.u32 %0, %%cluster_ctarank;" : "=r"(rank));

    // Each CTA covers 2048 contiguous elements = half of one batch.
    int base = (int)rank * 2048 + tid * 8;

    const float4* c4  = reinterpret_cast<const float4*>(contrast + base);
    const int4*   l4  = reinterpret_cast<const int4*>(label + base);
    const float4* a4  = reinterpret_cast<const float4*>(aux + base);
    const float4* al4 = reinterpret_cast<const float4*>(aux_label + base);

    // Issue all 8 loads up-front (MLP = 8).
    float4 c0  = c4[0],  c1  = c4[1];
    int4   l0  = l4[0],  l1  = l4[1];
    float4 a0  = a4[0],  a1  = a4[1];
    float4 al0 = al4[0], al1 = al4[1];

    float sn = 0.f, sp = 0.f, ax = 0.f;

    acc_elem(c0.x, l0.x, sn, sp);
    acc_elem(c0.y, l0.y, sn, sp);
    acc_elem(c0.z, l0.z, sn, sp);
    acc_elem(c0.w, l0.w, sn, sp);
    acc_elem(c1.x, l1.x, sn, sp);
    acc_elem(c1.y, l1.y, sn, sp);
    acc_elem(c1.z, l1.z, sn, sp);
    acc_elem(c1.w, l1.w, sn, sp);

    float d;
    d = a0.x - al0.x; ax = fmaf(d, d, ax);
    d = a0.y - al0.y; ax = fmaf(d, d, ax);
    d = a0.z - al0.z; ax = fmaf(d, d, ax);
    d = a0.w - al0.w; ax = fmaf(d, d, ax);
    d = a1.x - al1.x; ax = fmaf(d, d, ax);
    d = a1.y - al1.y; ax = fmaf(d, d, ax);
    d = a1.z - al1.z; ax = fmaf(d, d, ax);
    d = a1.w - al1.w; ax = fmaf(d, d, ax);

    // Warp reduction (8 warps per CTA).
    #pragma unroll
    for (int o = 16; o > 0; o >>= 1) {
        sn += __shfl_down_sync(FULL, sn, o);
        sp += __shfl_down_sync(FULL, sp, o);
        ax += __shfl_down_sync(FULL, ax, o);
    }

    // Each warp's lane 0 stores its partial DIRECTLY into rank 0's smem.
    if ((tid & 31) == 0) {
        int slot = (int)rank * (NTHR / 32) + (tid >> 5);
        uint32_t local = smem_u32(&sclus[slot]);
        uint32_t rem;
        asm volatile("mapa.shared::cluster.u32 %0, %1, 0;" : "=r"(rem) : "r"(local));
        asm volatile("st.shared::cluster.v4.f32 [%0], {%1, %2, %3, %4};"
                     :: "r"(rem), "f"(sn), "f"(sp), "f"(ax), "f"(0.f) : "memory");
    }

    // One cluster barrier: arrive (release) orders each lane0's DSMEM store;
    // wait (acquire) makes them visible to rank 0's readers.
    asm volatile("barrier.cluster.arrive.aligned;" ::: "memory");
    asm volatile("barrier.cluster.wait.aligned;"   ::: "memory");

    if (rank == 0 && tid < 32) {
        // 64 slots: batch b owns slots [16b, 16b+16) (ranks 2b, 2b+1).
        // Lane l: batch = l>>3, idx = l&7 -> loads slots 16b+idx, 16b+8+idx.
        int b   = tid >> 3;
        int idx = tid & 7;
        float4 p = sclus[16 * b + idx];
        float4 q = sclus[16 * b + 8 + idx];
        float bn = p.x + q.x;
        float bp = p.y + q.y;
        float ba = p.z + q.z;

        // Octet butterfly: lanes within an octet share a batch.
        #pragma unroll
        for (int o = 1; o < 8; o <<= 1) {
            bn += __shfl_xor_sync(FULL, bn, o);
            bp += __shfl_xor_sync(FULL, bp, o);
            ba += __shfl_xor_sync(FULL, ba, o);
        }

        // All 8 lanes of each octet now hold the batch sums; compute the
        // per-batch losses in parallel (4 concurrent MUFU chains).
        // Empty class -> bn or bp == 0 -> lse = -inf -> contras = 0.
        float lse     = __logf(bn) + __logf(bp);
        float contras = fmaxf(lse, 0.f) + log1pf(__expf(-fabsf(lse)));
        float laux    = ba * (1.0f / 4096.0f);

        // Keep only octet leaders, then butterfly across octets.
        if (idx != 0) { contras = 0.f; laux = 0.f; }
        contras += __shfl_xor_sync(FULL, contras, 8);
        laux    += __shfl_xor_sync(FULL, laux, 8);
        contras += __shfl_xor_sync(FULL, contras, 16);
        laux    += __shfl_xor_sync(FULL, laux, 16);

        if (tid == 0) {
            out[0] = contras * 0.25f;   // / n_items (B=4)
            out[1] = laux * 0.25f;
        }
    }
}

extern "C" void kernel_launch(void* const* d_in, const int* in_sizes, int n_in,
                              void* d_out, int out_size) {
    const float* contrast  = (const float*)d_in[0];
    const int*   label     = (const int*)d_in[1];
    const float* aux       = (const float*)d_in[2];
    const float* aux_label = (const float*)d_in[3];
    float* out = (float*)d_out;

    contrast_loss_kernel<<<NBLK, NTHR>>>(contrast, label, aux, aux_label, out);
}

// round 9
// speedup vs baseline: 1.1140x; 1.1140x over previous
#include <cuda_runtime.h>
#include <math.h>
#include <stdint.h>

// ContrastLoss: B=4, C=4096, K=1.
//
// lse_pairs_b   = log(sum_{lab=0} e^{pred}) + log(sum_{lab=1} e^{-pred})
// loss_contrast = (1/B) * sum_b logaddexp(lse_pairs_b, 0)
// loss_aux      = (1/B) * sum_b mean_c (aux - aux_label)^2
//
// R9 = R7 body (8-CTA cluster x 512 thr, 4 elems/thread: best measured)
//    + R8 tail  (per-warp DSMEM stores into rank 0, one cluster barrier,
//                fully parallel 128-slot final reduce in rank 0 warp 0).
// Deterministic: fixed slots, fixed butterfly order.

#define FULL 0xFFFFFFFFu
#define NBLK 8
#define NTHR 512
#define WPB  (NTHR / 32)            // 16 warps per CTA
#define NSLOT (NBLK * WPB)          // 128 slots

__device__ __forceinline__ uint32_t smem_u32(const void* p) {
    uint32_t a;
    asm("{ .reg .u64 t; cvta.to.shared.u64 t, %1; cvt.u32.u64 %0, t; }"
        : "=r"(a) : "l"(p));
    return a;
}

__device__ __forceinline__ void acc_elem(float v, int lab, float& sn, float& sp) {
    float fl = (float)lab;
    float e  = __expf(v * fmaf(-2.f, fl, 1.f));  // exp(+v) if lab==0 else exp(-v)
    sn = fmaf(e, 1.f - fl, sn);
    sp = fmaf(e, fl, sp);
}

__global__ __launch_bounds__(NTHR, 1) __cluster_dims__(NBLK, 1, 1)
void contrast_loss_kernel(const float* __restrict__ contrast,
                          const int*   __restrict__ label,
                          const float* __restrict__ aux,
                          const float* __restrict__ aux_label,
                          float* __restrict__ out) {
    // Only rank 0's copy is used; identical layout in every CTA so mapa
    // translates local slot addresses to rank 0's shared memory.
    __shared__ float4 sclus[NSLOT];

    int tid = threadIdx.x;
    uint32_t rank;
    asm("mov.u32 %0, %%cluster_ctarank;" : "=r"(rank));

    // Each CTA covers 2048 contiguous elements = half of one batch.
    int base = (int)rank * 2048 + tid * 4;

    float4 c  = *reinterpret_cast<const float4*>(contrast + base);
    int4   l  = *reinterpret_cast<const int4*>(label + base);
    float4 a  = *reinterpret_cast<const float4*>(aux + base);
    float4 al = *reinterpret_cast<const float4*>(aux_label + base);

    float sn = 0.f, sp = 0.f, ax = 0.f;

    acc_elem(c.x, l.x, sn, sp);
    acc_elem(c.y, l.y, sn, sp);
    acc_elem(c.z, l.z, sn, sp);
    acc_elem(c.w, l.w, sn, sp);

    float d;
    d = a.x - al.x; ax = fmaf(d, d, ax);
    d = a.y - al.y; ax = fmaf(d, d, ax);
    d = a.z - al.z; ax = fmaf(d, d, ax);
    d = a.w - al.w; ax = fmaf(d, d, ax);

    // Warp reduction (16 warps per CTA).
    #pragma unroll
    for (int o = 16; o > 0; o >>= 1) {
        sn += __shfl_down_sync(FULL, sn, o);
        sp += __shfl_down_sync(FULL, sp, o);
        ax += __shfl_down_sync(FULL, ax, o);
    }

    // Each warp's lane 0 stores its partial DIRECTLY into rank 0's smem.
    if ((tid & 31) == 0) {
        int slot = (int)rank * WPB + (tid >> 5);
        uint32_t local = smem_u32(&sclus[slot]);
        uint32_t rem;
        asm volatile("mapa.shared::cluster.u32 %0, %1, 0;" : "=r"(rem) : "r"(local));
        asm volatile("st.shared::cluster.v4.f32 [%0], {%1, %2, %3, %4};"
                     :: "r"(rem), "f"(sn), "f"(sp), "f"(ax), "f"(0.f) : "memory");
    }

    // One cluster barrier: arrive (release) orders the DSMEM stores;
    // wait (acquire) makes them visible to rank 0's readers.
    asm volatile("barrier.cluster.arrive.aligned;" ::: "memory");
    asm volatile("barrier.cluster.wait.aligned;"   ::: "memory");

    if (rank == 0 && tid < 32) {
        // 128 slots; CTA r (batch r>>1) owns slots [16r, 16r+16), so batch b
        // owns slots [32b, 32b+32). Lane l: batch = l>>3, idx = l&7;
        // reads 4 slots: 32b+idx, +8, +16, +24.
        int b   = tid >> 3;
        int idx = tid & 7;
        float4 p0 = sclus[32 * b + idx];
        float4 p1 = sclus[32 * b + idx + 8];
        float4 p2 = sclus[32 * b + idx + 16];
        float4 p3 = sclus[32 * b + idx + 24];
        float bn = (p0.x + p1.x) + (p2.x + p3.x);
        float bp = (p0.y + p1.y) + (p2.y + p3.y);
        float ba = (p0.z + p1.z) + (p2.z + p3.z);

        // Octet butterfly: lanes within an octet share a batch.
        #pragma unroll
        for (int o = 1; o < 8; o <<= 1) {
            bn += __shfl_xor_sync(FULL, bn, o);
            bp += __shfl_xor_sync(FULL, bp, o);
            ba += __shfl_xor_sync(FULL, ba, o);
        }

        // Per-batch losses computed in parallel across the 4 octets.
        // Empty class -> bn or bp == 0 -> lse = -inf -> contras = 0.
        float lse     = __logf(bn) + __logf(bp);
        float contras = fmaxf(lse, 0.f) + log1pf(__expf(-fabsf(lse)));
        float laux    = ba * (1.0f / 4096.0f);

        // Keep only octet leaders, then butterfly across octets.
        if (idx != 0) { contras = 0.f; laux = 0.f; }
        contras += __shfl_xor_sync(FULL, contras, 8);
        laux    += __shfl_xor_sync(FULL, laux, 8);
        contras += __shfl_xor_sync(FULL, contras, 16);
        laux    += __shfl_xor_sync(FULL, laux, 16);

        if (tid == 0) {
            out[0] = contras * 0.25f;   // / n_items (B=4)
            out[1] = laux * 0.25f;
        }
    }
}

extern "C" void kernel_launch(void* const* d_in, const int* in_sizes, int n_in,
                              void* d_out, int out_size) {
    const float* contrast  = (const float*)d_in[0];
    const int*   label     = (const int*)d_in[1];
    const float* aux       = (const float*)d_in[2];
    const float* aux_label = (const float*)d_in[3];
    float* out = (float*)d_out;

    contrast_loss_kernel<<<NBLK, NTHR>>>(contrast, label, aux, aux_label, out);
}